// round 1
// baseline (speedup 1.0000x reference)
#include <cuda_runtime.h>
#include <math.h>

#define TT 100
#define BB 64
#define II 256
#define HH 512
#define H3 1536
#define H4 2048

// ---------------- scratch (device globals: no allocation allowed) ----------------
__device__ float g_WihT[II * H4];                 // [256][2048]  W_ih^T
__device__ float g_WhhT[HH * H4];                 // [512][2048]  W_hh^T
__device__ float g_bias[H4];                      // b_ih + b_hh
__device__ float g_Gx[(size_t)TT * BB * H4];      // x_t @ W_ih^T + bias, [T][B][4H]
__device__ float g_h[(size_t)(TT + 1) * BB * HH]; // h history, g_h[0] = initial_h
__device__ float g_c[BB * HH];                    // running cell state
__device__ float g_f[(size_t)TT * BB * HH];       // f gate history
__device__ float g_d[(size_t)TT * BB * H3];       // d history -> overwritten with w = d * suffix-prod(f)
__device__ float g_gpart[8 * BB * H4];            // split-K partial sums (deterministic, no atomics)

// ---------------- prep: bias sum, copy h0/c0 ----------------
__global__ void prep_kernel(const float* __restrict__ h0, const float* __restrict__ c0,
                            const float* __restrict__ bih, const float* __restrict__ bhh) {
    int i = blockIdx.x * blockDim.x + threadIdx.x;  // grid covers BB*H4 = 131072
    if (i < H4) g_bias[i] = bih[i] + bhh[i];
    if (i < BB * HH) { g_h[i] = h0[i]; g_c[i] = c0[i]; }
}

// ---------------- transpose [R][C] -> [C][R] into g_WihT (which=0) or g_WhhT (which=1) ----------------
__global__ void transpose_kernel(const float* __restrict__ in, int R, int C, int which) {
    __shared__ float s[32][33];
    float* out = which ? g_WhhT : g_WihT;
    int c0 = blockIdx.x * 32, r0 = blockIdx.y * 32;
    int tx = threadIdx.x, ty = threadIdx.y;
    for (int i = ty; i < 32; i += 8)
        s[i][tx] = in[(size_t)(r0 + i) * C + c0 + tx];
    __syncthreads();
    for (int i = ty; i < 32; i += 8)
        out[(size_t)(c0 + i) * R + r0 + tx] = s[tx][i];
}

// ---------------- Gx = X[6400,256] @ WihT[256,2048] + bias ----------------
// 64x64 block tile, 256 threads, 4x4 per thread, BK=16
__global__ void gx_kernel(const float* __restrict__ X) {
    __shared__ __align__(16) float As[16][68];
    __shared__ __align__(16) float Bs[16][64];
    const int tid = threadIdx.x;
    const int m0 = blockIdx.y * 64;     // 100 tiles
    const int n0 = blockIdx.x * 64;     // 32 tiles
    const int tm = (tid >> 4) * 4, tn = (tid & 15) * 4;
    const int am = tid >> 2, ak = (tid & 3) * 4;
    const int bk = tid >> 4, bn = (tid & 15) * 4;
    float acc[4][4] = {};
    for (int k0 = 0; k0 < II; k0 += 16) {
        float4 av = *(const float4*)(X + (size_t)(m0 + am) * II + k0 + ak);
        As[ak + 0][am] = av.x; As[ak + 1][am] = av.y; As[ak + 2][am] = av.z; As[ak + 3][am] = av.w;
        *(float4*)&Bs[bk][bn] = *(const float4*)(g_WihT + (size_t)(k0 + bk) * H4 + n0 + bn);
        __syncthreads();
#pragma unroll
        for (int kk = 0; kk < 16; kk++) {
            float4 a = *(const float4*)&As[kk][tm];
            float4 b = *(const float4*)&Bs[kk][tn];
            acc[0][0] += a.x * b.x; acc[0][1] += a.x * b.y; acc[0][2] += a.x * b.z; acc[0][3] += a.x * b.w;
            acc[1][0] += a.y * b.x; acc[1][1] += a.y * b.y; acc[1][2] += a.y * b.z; acc[1][3] += a.y * b.w;
            acc[2][0] += a.z * b.x; acc[2][1] += a.z * b.y; acc[2][2] += a.z * b.z; acc[2][3] += a.z * b.w;
            acc[3][0] += a.w * b.x; acc[3][1] += a.w * b.y; acc[3][2] += a.w * b.z; acc[3][3] += a.w * b.w;
        }
        __syncthreads();
    }
    float4 bias4 = *(const float4*)(g_bias + n0 + tn);
#pragma unroll
    for (int i = 0; i < 4; i++) {
        float4 v;
        v.x = acc[i][0] + bias4.x; v.y = acc[i][1] + bias4.y;
        v.z = acc[i][2] + bias4.z; v.w = acc[i][3] + bias4.w;
        *(float4*)(g_Gx + (size_t)(m0 + tm + i) * H4 + n0 + tn) = v;
    }
}

// ---------------- per-step recurrent GEMM: h_t[64,512] @ WhhT[512,2048], split-K=8 ----------------
// grid (32 n-tiles, 8 k-chunks), 256 threads, 64x64 tile, 4x4 per thread
__global__ void step_gemm_kernel(int t) {
    __shared__ __align__(16) float As[16][68];
    __shared__ __align__(16) float Bs[16][64];
    const float* __restrict__ Ag = g_h + (size_t)t * BB * HH;
    const int tid = threadIdx.x;
    const int n0 = blockIdx.x * 64;
    const int kc = blockIdx.y;
    const int tm = (tid >> 4) * 4, tn = (tid & 15) * 4;
    const int am = tid >> 2, ak = (tid & 3) * 4;
    const int bk = tid >> 4, bn = (tid & 15) * 4;
    float acc[4][4] = {};
    const int kend = kc * 64 + 64;
    for (int k0 = kc * 64; k0 < kend; k0 += 16) {
        float4 av = *(const float4*)(Ag + (size_t)am * HH + k0 + ak);
        As[ak + 0][am] = av.x; As[ak + 1][am] = av.y; As[ak + 2][am] = av.z; As[ak + 3][am] = av.w;
        *(float4*)&Bs[bk][bn] = *(const float4*)(g_WhhT + (size_t)(k0 + bk) * H4 + n0 + bn);
        __syncthreads();
#pragma unroll
        for (int kk = 0; kk < 16; kk++) {
            float4 a = *(const float4*)&As[kk][tm];
            float4 b = *(const float4*)&Bs[kk][tn];
            acc[0][0] += a.x * b.x; acc[0][1] += a.x * b.y; acc[0][2] += a.x * b.z; acc[0][3] += a.x * b.w;
            acc[1][0] += a.y * b.x; acc[1][1] += a.y * b.y; acc[1][2] += a.y * b.z; acc[1][3] += a.y * b.w;
            acc[2][0] += a.z * b.x; acc[2][1] += a.z * b.y; acc[2][2] += a.z * b.z; acc[2][3] += a.z * b.w;
            acc[3][0] += a.w * b.x; acc[3][1] += a.w * b.y; acc[3][2] += a.w * b.z; acc[3][3] += a.w * b.w;
        }
        __syncthreads();
    }
    float* dst = g_gpart + (size_t)kc * BB * H4;
#pragma unroll
    for (int i = 0; i < 4; i++) {
        float4 v = make_float4(acc[i][0], acc[i][1], acc[i][2], acc[i][3]);
        *(float4*)(dst + (size_t)(tm + i) * H4 + n0 + tn) = v;
    }
}

// ---------------- pointwise LSTM cell + e-prop derivative capture ----------------
__global__ void cell_kernel(int t, float* __restrict__ out_h, float* __restrict__ out_c) {
    int idx = blockIdx.x * blockDim.x + threadIdx.x;  // < BB*HH
    int b = idx >> 9;        // /512
    int h = idx & (HH - 1);
    size_t gb = (size_t)b * H4 + h;
    size_t xb = (size_t)t * BB * H4 + gb;
    float gi = g_Gx[xb], gf = g_Gx[xb + HH], gg = g_Gx[xb + 2 * HH], go = g_Gx[xb + 3 * HH];
#pragma unroll
    for (int kc = 0; kc < 8; kc++) {
        size_t pb = (size_t)kc * BB * H4 + gb;
        gi += g_gpart[pb];
        gf += g_gpart[pb + HH];
        gg += g_gpart[pb + 2 * HH];
        go += g_gpart[pb + 3 * HH];
    }
    float i = 1.f / (1.f + expf(-gi));
    float f = 1.f / (1.f + expf(-gf));
    float g = tanhf(gg);
    float o = 1.f / (1.f + expf(-go));
    float cx = g_c[idx];
    float cy = f * cx + i * g;
    float hy = o * tanhf(cy);
    g_c[idx] = cy;
    g_h[(size_t)(t + 1) * BB * HH + idx] = hy;
    out_h[(size_t)t * BB * HH + idx] = hy;
    g_f[(size_t)t * BB * HH + idx] = f;
    size_t db = (size_t)t * BB * H3 + (size_t)b * H3 + h;
    g_d[db]          = g * i * (1.f - i);
    g_d[db + HH]     = cx * f * (1.f - f);
    g_d[db + 2 * HH] = i * (1.f - g) * (1.f + g);
    if (out_c) out_c[idx] = cy;
}

// ---------------- reverse suffix-product scan: w_t = d_t * prod_{s>t} f_s ; ev_b = sum_t w_t ----------------
__global__ void scan_kernel(float* __restrict__ evb_out) {
    int idx = blockIdx.x * blockDim.x + threadIdx.x;  // < BB*H3
    int b = idx / H3, j = idx % H3;
    int h = j & (HH - 1);  // j mod H (f3 = tile(f,3))
    float p = 1.f, sum = 0.f;
    for (int t = TT - 1; t >= 0; t--) {
        size_t di = (size_t)t * BB * H3 + (size_t)b * H3 + j;
        float w = g_d[di] * p;
        g_d[di] = w;
        sum += w;
        p *= g_f[(size_t)t * BB * HH + (size_t)b * HH + h];
    }
    evb_out[idx] = sum;
}

// ---------------- batched ev GEMM: out[b][j][k] = sum_t w[t][b][j] * Xs[t][b][k] ----------------
// K = T = 100. 128x128 tile, 256 threads, 8x8 per thread, BT=8. Xs==nullptr -> use g_h (h_{t-1} history).
__global__ void ev_kernel(const float* __restrict__ Xs, int kdim, float* __restrict__ out) {
    __shared__ __align__(16) float Ws[8][128];
    __shared__ __align__(16) float Bs[8][128];
    if (Xs == nullptr) Xs = g_h;  // ev_hh: h_{t-1} = g_h[t] slice
    const int tid = threadIdx.x;
    const int b = blockIdx.z;
    const int j0 = blockIdx.y * 128;
    const int k0 = blockIdx.x * 128;
    const int tj = (tid >> 4) * 8, tk = (tid & 15) * 8;
    const int ltt = tid >> 5;          // 0..7
    const int lj = (tid & 31) * 4;     // 0..124
    float acc[8][8] = {};
    for (int t0 = 0; t0 < TT; t0 += 8) {
        int t = t0 + ltt;
        float4 wv = make_float4(0.f, 0.f, 0.f, 0.f);
        float4 xv = make_float4(0.f, 0.f, 0.f, 0.f);
        if (t < TT) {
            wv = *(const float4*)(g_d + (size_t)t * BB * H3 + (size_t)b * H3 + j0 + lj);
            xv = *(const float4*)(Xs + ((size_t)t * BB + b) * kdim + k0 + lj);
        }
        *(float4*)&Ws[ltt][lj] = wv;
        *(float4*)&Bs[ltt][lj] = xv;
        __syncthreads();
#pragma unroll
        for (int u = 0; u < 8; u++) {
            float4 a0 = *(const float4*)&Ws[u][tj];
            float4 a1 = *(const float4*)&Ws[u][tj + 4];
            float4 b0 = *(const float4*)&Bs[u][tk];
            float4 b1 = *(const float4*)&Bs[u][tk + 4];
            float aa[8] = {a0.x, a0.y, a0.z, a0.w, a1.x, a1.y, a1.z, a1.w};
            float bb[8] = {b0.x, b0.y, b0.z, b0.w, b1.x, b1.y, b1.z, b1.w};
#pragma unroll
            for (int i = 0; i < 8; i++)
#pragma unroll
                for (int j = 0; j < 8; j++)
                    acc[i][j] += aa[i] * bb[j];
        }
        __syncthreads();
    }
#pragma unroll
    for (int i = 0; i < 8; i++) {
        float* orow = out + ((size_t)b * H3 + j0 + tj + i) * kdim + k0 + tk;
        *(float4*)orow = make_float4(acc[i][0], acc[i][1], acc[i][2], acc[i][3]);
        *(float4*)(orow + 4) = make_float4(acc[i][4], acc[i][5], acc[i][6], acc[i][7]);
    }
}

// ---------------- launch ----------------
extern "C" void kernel_launch(void* const* d_in, const int* in_sizes, int n_in,
                              void* d_out, int out_size) {
    (void)in_sizes; (void)n_in; (void)out_size;
    const float* input = (const float*)d_in[0];   // [T,B,I]
    const float* h0    = (const float*)d_in[1];   // [B,H]
    const float* c0    = (const float*)d_in[2];   // [B,H]
    const float* wih   = (const float*)d_in[3];   // [4H,I]
    const float* whh   = (const float*)d_in[4];   // [4H,H]
    const float* bih   = (const float*)d_in[5];   // [4H]
    const float* bhh   = (const float*)d_in[6];   // [4H]

    float* out         = (float*)d_out;
    float* out_outputs = out;                                   // T*B*H
    float* out_cx      = out_outputs + (size_t)TT * BB * HH;    // B*H
    float* out_evih    = out_cx + (size_t)BB * HH;              // B*3H*I
    float* out_evhh    = out_evih + (size_t)BB * H3 * II;       // B*3H*H
    float* out_evb     = out_evhh + (size_t)BB * H3 * HH;       // B*3H

    prep_kernel<<<512, 256>>>(h0, c0, bih, bhh);
    transpose_kernel<<<dim3(II / 32, H4 / 32), dim3(32, 8)>>>(wih, H4, II, 0);
    transpose_kernel<<<dim3(HH / 32, H4 / 32), dim3(32, 8)>>>(whh, H4, HH, 1);
    gx_kernel<<<dim3(32, 100), 256>>>(input);

    for (int t = 0; t < TT; t++) {
        step_gemm_kernel<<<dim3(32, 8), 256>>>(t);
        cell_kernel<<<128, 256>>>(t, out_outputs, (t == TT - 1) ? out_cx : nullptr);
    }

    scan_kernel<<<BB * H3 / 256, 256>>>(out_evb);
    ev_kernel<<<dim3(II / 128, H3 / 128, BB), 256>>>(input, II, out_evih);
    ev_kernel<<<dim3(HH / 128, H3 / 128, BB), 256>>>(nullptr, HH, out_evhh);
}